// round 8
// baseline (speedup 1.0000x reference)
#include <cuda_runtime.h>
#include <cuda_bf16.h>
#include <cstdint>

// Problem constants
#define B_    2
#define L_    512
#define V_    32000
#define TWOV  64000
#define MAXM  4096
#define NT2   500            // 64000/128 vocab tiles

// ---------------- GEMM1 (mma.sync bf16) tiling ----------------
#define BM 128
#define BN 128
#define BK 32
#define SA 40
#define SB 136
#define STAGES 4
#define A_ST (BM * SA * 2)
#define B_ST (BK * SB * 2)
#define G1_SMEM (STAGES * (A_ST + B_ST))

// ---------------- GEMM2 (fp8 mma.sync, persistent, 512 thr) ----------------
#define SA8   144                        // A row stride: 128 fp8 + 16 pad
#define SB8   528                        // B row stride: 512 fp8 + 16 pad
#define A8_ST (128 * SA8)                // 18432 B per A stage (BK=128 fp8)
#define B8_BYTES (128 * SB8)             // 67584  (128 N rows x 512 K fp8)
#define G2_SCR (B8_BYTES + 4 * A8_ST)    // 141312
#define G2_SMEM (G2_SCR + 4608)          // 145920
#define INV64 0.015625f

// ---------------- device scratch ----------------
static __device__ __align__(256) __nv_bfloat16 g_fbB[MAXM * 1024];
static __device__ __align__(256) __nv_bfloat16 g_w1B[1024 * 512];
static __device__ __align__(256) uint8_t       g_w2T8[(size_t)TWOV * 512];  // e4m3, x64
static __device__ __align__(256) float         g_h32[MAXM * 512];
static __device__ __align__(256) uint8_t       g_hF8[MAXM * 512];           // e4m3
static __device__ __align__(256) float         g_pm [MAXM * NT2];
static __device__ __align__(256) float         g_ps [MAXM * NT2];
static __device__ __align__(256) float         g_nll[MAXM * 2];

// ---------------- PTX helpers ----------------
__device__ __forceinline__ void cpa16(unsigned s, const void* g) {
    asm volatile("cp.async.cg.shared.global [%0], [%1], 16;\n" :: "r"(s), "l"(g));
}
__device__ __forceinline__ void cp_commit() { asm volatile("cp.async.commit_group;\n"); }
template<int N> __device__ __forceinline__ void cp_wait() {
    asm volatile("cp.async.wait_group %0;\n" :: "n"(N));
}
__device__ __forceinline__ void ldsmx4(unsigned* r, unsigned a) {
    asm volatile("ldmatrix.sync.aligned.m8n8.x4.shared.b16 {%0,%1,%2,%3}, [%4];\n"
                 : "=r"(r[0]), "=r"(r[1]), "=r"(r[2]), "=r"(r[3]) : "r"(a));
}
__device__ __forceinline__ void ldsmx4t(unsigned* r, unsigned a) {
    asm volatile("ldmatrix.sync.aligned.m8n8.x4.trans.shared.b16 {%0,%1,%2,%3}, [%4];\n"
                 : "=r"(r[0]), "=r"(r[1]), "=r"(r[2]), "=r"(r[3]) : "r"(a));
}
__device__ __forceinline__ void mma16816(float* c, const unsigned* a, const unsigned* b) {
    asm volatile(
        "mma.sync.aligned.m16n8k16.row.col.f32.bf16.bf16.f32 "
        "{%0,%1,%2,%3}, {%4,%5,%6,%7}, {%8,%9}, {%0,%1,%2,%3};\n"
        : "+f"(c[0]), "+f"(c[1]), "+f"(c[2]), "+f"(c[3])
        : "r"(a[0]), "r"(a[1]), "r"(a[2]), "r"(a[3]), "r"(b[0]), "r"(b[1]));
}
__device__ __forceinline__ void mma16832(float* c, const unsigned* a, const unsigned* b) {
    asm volatile(
        "mma.sync.aligned.m16n8k32.row.col.f32.e4m3.e4m3.f32 "
        "{%0,%1,%2,%3}, {%4,%5,%6,%7}, {%8,%9}, {%0,%1,%2,%3};\n"
        : "+f"(c[0]), "+f"(c[1]), "+f"(c[2]), "+f"(c[3])
        : "r"(a[0]), "r"(a[1]), "r"(a[2]), "r"(a[3]), "r"(b[0]), "r"(b[1]));
}
__device__ __forceinline__ unsigned short f2e4m3x2(float lo, float hi) {
    unsigned short r;
    asm("cvt.rn.satfinite.e4m3x2.f32 %0, %1, %2;" : "=h"(r) : "f"(hi), "f"(lo));
    return r;
}

// ---------------- fp32 -> bf16 (w1) ----------------
__global__ void k_f2bf(const float* __restrict__ src, int n4) {
    int i = blockIdx.x * blockDim.x + threadIdx.x;
    int stride = gridDim.x * blockDim.x;
    for (; i < n4; i += stride) {
        float4 v = reinterpret_cast<const float4*>(src)[i];
        reinterpret_cast<__nv_bfloat162*>(g_w1B)[2 * i]     = __floats2bfloat162_rn(v.x, v.y);
        reinterpret_cast<__nv_bfloat162*>(g_w1B)[2 * i + 1] = __floats2bfloat162_rn(v.z, v.w);
    }
}

// ---------------- w2 [512,64000] f32 -> w2T8 [64000,512] e4m3 (x64) ----------------
__global__ void k_w2t8(const float* __restrict__ w2) {
    __shared__ float t[64][65];
    int n0 = blockIdx.x * 64, k0 = blockIdx.y * 64;
    for (int i = threadIdx.x; i < 64 * 64; i += 256) {
        int r = i >> 6, c = i & 63;                    // r = k local, c = n local
        t[r][c] = w2[(size_t)(k0 + r) * TWOV + n0 + c];
    }
    __syncthreads();
    for (int i = threadIdx.x; i < 64 * 32; i += 256) {
        int r = i >> 5, c2 = (i & 31) * 2;             // r = n local, c2 = k local pair
        unsigned short p = f2e4m3x2(t[c2][r] * 64.f, t[c2 + 1][r] * 64.f);
        *reinterpret_cast<unsigned short*>(g_w2T8 + (size_t)(n0 + r) * 512 + k0 + c2) = p;
    }
}

// ---------------- gather fb rows -> bf16, zero-pad ----------------
__global__ void k_gather(const float* __restrict__ fwd, const float* __restrict__ bwd,
                         const int* __restrict__ fi, const int* __restrict__ bi,
                         int Np, int M) {
    int row = blockIdx.x;
    if (row < M) {
        int b = row / Np;
        int n = row - b * Np;
        const float* fsrc = fwd + ((size_t)b * L_ + fi[n]) * 512;
        const float* bsrc = bwd + ((size_t)b * L_ + bi[n]) * 512;
        for (int c = threadIdx.x; c < 1024; c += blockDim.x) {
            float v = (c < 512) ? fsrc[c] : bsrc[c - 512];
            g_fbB[(size_t)row * 1024 + c] = __float2bfloat16(v);
        }
    } else {
        for (int c = threadIdx.x; c < 1024; c += blockDim.x)
            g_fbB[(size_t)row * 1024 + c] = __float2bfloat16(0.f);
    }
}

// ---------------- GEMM1: h = leaky_relu(fb @ w1 + b1)  (bf16 mma.sync) ----------------
__global__ __launch_bounds__(256) void k_gemm1(const float* __restrict__ b1) {
    extern __shared__ char smem[];
    unsigned sb = (unsigned)__cvta_generic_to_shared(smem);
    const unsigned A0 = sb;
    const unsigned B0 = sb + STAGES * A_ST;
    const int tid = threadIdx.x, lane = tid & 31, wid = tid >> 5;
    const int wm = wid >> 2, wn = wid & 3;
    const int row0 = blockIdx.y * BM, col0 = blockIdx.x * BN;

    const unsigned aoff = ((wm * 64 + (lane & 15)) * SA + (lane >> 4) * 8) * 2;
    const unsigned boff = ((lane & 15) * SB + wn * 32 + (lane >> 4) * 8) * 2;

    float acc[4][4][4];
#pragma unroll
    for (int a = 0; a < 4; a++)
#pragma unroll
        for (int b = 0; b < 4; b++)
#pragma unroll
            for (int c = 0; c < 4; c++) acc[a][b][c] = 0.f;

    auto loadAB = [&](int st, int kk) {
#pragma unroll
        for (int i = 0; i < 2; i++) {
            int r = i * 64 + (tid >> 2), c = (tid & 3) * 8;
            cpa16(A0 + st * A_ST + (unsigned)(r * SA + c) * 2,
                  g_fbB + (size_t)(row0 + r) * 1024 + kk * BK + c);
        }
#pragma unroll
        for (int i = 0; i < 2; i++) {
            int r = i * 16 + (tid >> 4), c = (tid & 15) * 8;
            cpa16(B0 + st * B_ST + (unsigned)(r * SB + c) * 2,
                  g_w1B + (size_t)(kk * BK + r) * 512 + col0 + c);
        }
    };

    const int KT = 1024 / BK;
#pragma unroll
    for (int s = 0; s < STAGES - 1; s++) { loadAB(s, s); cp_commit(); }

    for (int kt = 0; kt < KT; kt++) {
        cp_wait<STAGES - 2>();
        __syncthreads();
        int kl = kt + STAGES - 1;
        if (kl < KT) loadAB(kl & (STAGES - 1), kl);
        cp_commit();
        int st = kt & (STAGES - 1);
        unsigned aS = A0 + st * A_ST + aoff;
        unsigned bS = B0 + st * B_ST + boff;
#pragma unroll
        for (int ks = 0; ks < 2; ks++) {
            unsigned afr[4][4], bfr[2][4];
#pragma unroll
            for (int mf = 0; mf < 4; mf++) ldsmx4(afr[mf], aS + mf * (16 * SA * 2) + ks * 32);
#pragma unroll
            for (int p = 0; p < 2; p++) ldsmx4t(bfr[p], bS + ks * (16 * SB * 2) + p * 32);
#pragma unroll
            for (int mf = 0; mf < 4; mf++) {
                mma16816(acc[mf][0], afr[mf], &bfr[0][0]);
                mma16816(acc[mf][1], afr[mf], &bfr[0][2]);
                mma16816(acc[mf][2], afr[mf], &bfr[1][0]);
                mma16816(acc[mf][3], afr[mf], &bfr[1][2]);
            }
        }
    }

    const int g = lane >> 2, q = lane & 3;
#pragma unroll
    for (int mf = 0; mf < 4; mf++) {
#pragma unroll
        for (int nf = 0; nf < 4; nf++) {
            int cl = col0 + wn * 32 + nf * 8 + q * 2;
#pragma unroll
            for (int rh = 0; rh < 2; rh++) {
                int rr = row0 + wm * 64 + mf * 16 + g + rh * 8;
                float v0 = acc[mf][nf][rh * 2 + 0] + b1[cl];
                float v1 = acc[mf][nf][rh * 2 + 1] + b1[cl + 1];
                v0 = v0 > 0.f ? v0 : 0.01f * v0;
                v1 = v1 > 0.f ? v1 : 0.01f * v1;
                g_h32[(size_t)rr * 512 + cl]     = v0;
                g_h32[(size_t)rr * 512 + cl + 1] = v1;
                *reinterpret_cast<unsigned short*>(g_hF8 + (size_t)rr * 512 + cl) =
                    f2e4m3x2(v0, v1);
            }
        }
    }
}

// ---------------- GEMM2: fp8 persistent, 16 warps 32x32, BK=128, streaming lse ----------------
__global__ __launch_bounds__(512, 1) void k_gemm2(const float* __restrict__ b2,
                                                  int MT, int NTASK) {
    extern __shared__ char smem[];
    unsigned sb = (unsigned)__cvta_generic_to_shared(smem);
    const unsigned Bb = sb;
    const unsigned Ab = sb + B8_BYTES;
    float* red_m  = (float*)(smem + G2_SCR);   // [4][128]
    float* red_s  = red_m + 512;               // [4][128]
    float* rowmax = red_s + 512;               // [128]

    const int tid = threadIdx.x, lane = tid & 31, wid = tid >> 5;
    const int wm = wid >> 2, wn = wid & 3;      // 4x4 warp grid, 32x32 tiles
    const int g = lane >> 2, q = lane & 3;

    const int t0 = (int)(((long long)blockIdx.x * NTASK) / gridDim.x);
    const int t1 = (int)(((long long)(blockIdx.x + 1) * NTASK) / gridDim.x);
    const int ntask = t1 - t0;
    if (ntask <= 0) return;
    const int NC = ntask * 4;                   // 4 A chunks (k128) per task

    // A ldmatrix lane addr: row = lane&15, 16B-col = lane>>4
    const unsigned aoff = (unsigned)(wm * 32 + (lane & 15)) * SA8 + (lane >> 4) * 16;
    // B ldmatrix (non-trans) lane addr: n_local + 16B k-col
    const int nlo = ((lane >> 4) & 1) * 8 + (lane & 7);
    const unsigned boff = (unsigned)(wn * 32 + nlo) * SB8 + ((lane >> 3) & 1) * 16;

    auto loadA = [&](int st, int cc) {
        int t = t0 + (cc >> 2), kt = cc & 3;
        int rb = t % MT;
        const uint8_t* base = g_hF8 + (size_t)(rb * 128) * 512 + kt * 128;
#pragma unroll
        for (int i = 0; i < 2; i++) {
            int idx = tid + i * 512;
            int r = idx >> 3, c16 = (idx & 7) * 16;
            cpa16(Ab + st * A8_ST + (unsigned)(r * SA8 + c16), base + (size_t)r * 512 + c16);
        }
    };

    float bv[4][2];
    int cur_ct = -1;
    int c = 0;
    bool first = true;

    for (int ti = 0; ti < ntask; ti++) {
        const int t = t0 + ti;
        const int ct = t / MT;
        const int rb = t - ct * MT;
        const int col0 = ct * 128;

        if (ct != cur_ct) {
            cur_ct = ct;
            cp_wait<0>();
            __syncthreads();
            // load B slice: 128 N rows x 512 K fp8 from g_w2T8
#pragma unroll
            for (int i = 0; i < 8; i++) {
                int idx = tid + i * 512;
                int r = idx >> 5, c16 = (idx & 31) * 16;
                cpa16(Bb + (unsigned)(r * SB8 + c16),
                      g_w2T8 + (size_t)(col0 + r) * 512 + c16);
            }
            cp_commit();
#pragma unroll
            for (int nf = 0; nf < 4; nf++) {
                int cc2 = col0 + wn * 32 + nf * 8 + q * 2;
                bv[nf][0] = b2[cc2];
                bv[nf][1] = b2[cc2 + 1];
            }
            cp_wait<0>();
            __syncthreads();
        }

        if (first) {
            first = false;
#pragma unroll
            for (int s = 0; s < 3; s++) { loadA(s, s); cp_commit(); }
        }

        float acc[2][4][4];
#pragma unroll
        for (int a = 0; a < 2; a++)
#pragma unroll
            for (int b = 0; b < 4; b++)
#pragma unroll
                for (int e = 0; e < 4; e++) acc[a][b][e] = 0.f;

        for (int kt = 0; kt < 4; kt++, c++) {
            cp_wait<2>();
            __syncthreads();
            int cl = c + 3;
            if (cl < NC) loadA(cl & 3, cl);
            cp_commit();
            unsigned aS = Ab + (c & 3) * A8_ST + aoff;
            unsigned bS = Bb + (unsigned)(kt * 128) + boff;
#pragma unroll
            for (int ks = 0; ks < 4; ks++) {
                unsigned afr[2][4], bfr[2][4];
#pragma unroll
                for (int mf = 0; mf < 2; mf++)
                    ldsmx4(afr[mf], aS + mf * (16 * SA8) + ks * 32);
#pragma unroll
                for (int h = 0; h < 2; h++)
                    ldsmx4(bfr[h], bS + h * (16 * SB8) + ks * 32);
#pragma unroll
                for (int mf = 0; mf < 2; mf++) {
                    mma16832(acc[mf][0], afr[mf], &bfr[0][0]);
                    mma16832(acc[mf][1], afr[mf], &bfr[0][2]);
                    mma16832(acc[mf][2], afr[mf], &bfr[1][0]);
                    mma16832(acc[mf][3], afr[mf], &bfr[1][2]);
                }
            }
        }

        // ---- epilogue: per-row tile max + sumexp partials ----
        __syncthreads();
#pragma unroll
        for (int mf = 0; mf < 2; mf++) {
#pragma unroll
            for (int rh = 0; rh < 2; rh++) {
                float m = -1e30f;
#pragma unroll
                for (int nf = 0; nf < 4; nf++) {
                    m = fmaxf(m, fmaf(acc[mf][nf][rh * 2 + 0], INV64, bv[nf][0]));
                    m = fmaxf(m, fmaf(acc[mf][nf][rh * 2 + 1], INV64, bv[nf][1]));
                }
                m = fmaxf(m, __shfl_xor_sync(0xffffffffu, m, 1));
                m = fmaxf(m, __shfl_xor_sync(0xffffffffu, m, 2));
                if (q == 0) red_m[wn * 128 + wm * 32 + mf * 16 + rh * 8 + g] = m;
            }
        }
        __syncthreads();
        if (tid < 128)
            rowmax[tid] = fmaxf(fmaxf(red_m[tid], red_m[128 + tid]),
                                fmaxf(red_m[256 + tid], red_m[384 + tid]));
        __syncthreads();
#pragma unroll
        for (int mf = 0; mf < 2; mf++) {
#pragma unroll
            for (int rh = 0; rh < 2; rh++) {
                int rl = wm * 32 + mf * 16 + rh * 8 + g;
                float rm = rowmax[rl];
                float s = 0.f;
#pragma unroll
                for (int nf = 0; nf < 4; nf++) {
                    s += __expf(fmaf(acc[mf][nf][rh * 2 + 0], INV64, bv[nf][0]) - rm);
                    s += __expf(fmaf(acc[mf][nf][rh * 2 + 1], INV64, bv[nf][1]) - rm);
                }
                s += __shfl_xor_sync(0xffffffffu, s, 1);
                s += __shfl_xor_sync(0xffffffffu, s, 2);
                if (q == 0) red_s[wn * 128 + rl] = s;
            }
        }
        __syncthreads();
        if (tid < 128) {
            float s = red_s[tid] + red_s[128 + tid] + red_s[256 + tid] + red_s[384 + tid];
            int rowg = rb * 128 + tid;
            g_pm[(size_t)rowg * NT2 + ct] = rowmax[tid];
            g_ps[(size_t)rowg * NT2 + ct] = s;
        }
        __syncthreads();
    }
}

// ---------------- per-(row,branch) lse merge + label logit + nll ----------------
__global__ void k_reduce(const int* __restrict__ seq, const int* __restrict__ fi,
                         const int* __restrict__ bi, const float* __restrict__ w2,
                         const float* __restrict__ b2, int Np, int M) {
    int gw = (blockIdx.x * blockDim.x + threadIdx.x) >> 5;
    int lane = threadIdx.x & 31;
    if (gw >= M * 2) return;
    int r = gw >> 1, br = gw & 1;
    int b = r / Np, n = r - b * Np;
    int pos = br ? bi[n] : fi[n];
    int label = seq[b * L_ + pos];
    int col = br * V_ + label;

    const float* pm = g_pm + (size_t)r * NT2 + br * 250;
    const float* ps = g_ps + (size_t)r * NT2 + br * 250;
    float m = -1e30f;
    for (int i = lane; i < 250; i += 32) m = fmaxf(m, pm[i]);
#pragma unroll
    for (int o = 16; o; o >>= 1) m = fmaxf(m, __shfl_xor_sync(0xffffffffu, m, o));
    float s = 0.f;
    for (int i = lane; i < 250; i += 32) s += ps[i] * __expf(pm[i] - m);
#pragma unroll
    for (int o = 16; o; o >>= 1) s += __shfl_xor_sync(0xffffffffu, s, o);
    float lse = m + logf(s);

    float dot = 0.f;
    for (int k = lane; k < 512; k += 32)
        dot += g_h32[(size_t)r * 512 + k] * w2[(size_t)k * TWOV + col];
#pragma unroll
    for (int o = 16; o; o >>= 1) dot += __shfl_xor_sync(0xffffffffu, dot, o);

    if (lane == 0) {
        float nll = lse - (dot + b2[col]);
        g_nll[gw] = nll * (br ? 0.25f : 1.0f);
    }
}

// ---------------- deterministic final mean ----------------
__global__ void k_final(float* __restrict__ out, int M) {
    __shared__ float sh[256];
    float s = 0.f;
    for (int i = threadIdx.x; i < 2 * M; i += 256) s += g_nll[i];
    sh[threadIdx.x] = s;
    __syncthreads();
    for (int o = 128; o; o >>= 1) {
        if (threadIdx.x < o) sh[threadIdx.x] += sh[threadIdx.x + o];
        __syncthreads();
    }
    if (threadIdx.x == 0) out[0] = sh[0] / (float)(2 * M);
}

// ---------------- launch ----------------
extern "C" void kernel_launch(void* const* d_in, const int* in_sizes, int n_in,
                              void* d_out, int out_size) {
    const float* fwd = (const float*)d_in[0];
    const float* bwd = (const float*)d_in[1];
    const int*   seq = (const int*)  d_in[2];
    const int*   fi  = (const int*)  d_in[3];
    const int*   bi  = (const int*)  d_in[4];
    const float* w1  = (const float*)d_in[5];
    const float* b1  = (const float*)d_in[6];
    const float* w2  = (const float*)d_in[7];
    const float* b2  = (const float*)d_in[8];

    int Np = in_sizes[3];
    int M  = B_ * Np;
    int MT = (M + BM - 1) / BM;       // 128-row blocks
    int Mpad = MT * BM;

    int nsm = 148;
    cudaDeviceGetAttribute(&nsm, cudaDevAttrMultiProcessorCount, 0);
    int NTASK = NT2 * MT;
    int grid2 = nsm < NTASK ? nsm : NTASK;

    cudaFuncSetAttribute(k_gemm1, cudaFuncAttributeMaxDynamicSharedMemorySize, G1_SMEM);
    cudaFuncSetAttribute(k_gemm2, cudaFuncAttributeMaxDynamicSharedMemorySize, G2_SMEM);

    k_f2bf<<<256, 256>>>(w1, (1024 * 512) / 4);
    k_w2t8<<<dim3(TWOV / 64, 512 / 64), 256>>>(w2);
    k_gather<<<Mpad, 256>>>(fwd, bwd, fi, bi, Np, M);

    dim3 g1(512 / BN, MT);
    k_gemm1<<<g1, 256, G1_SMEM>>>(b1);

    k_gemm2<<<grid2, 512, G2_SMEM>>>(b2, MT, NTASK);

    int warps = M * 2;
    int blocks = (warps * 32 + 255) / 256;
    k_reduce<<<blocks, 256>>>(seq, fi, bi, w2, b2, Np, M);
    k_final<<<1, 256>>>((float*)d_out, M);
}